// round 1
// baseline (speedup 1.0000x reference)
#include <cuda_runtime.h>

#define BATCH 256
#define NROWS 256
#define MCOLS 256
#define DDIM  32
#define RR    2            // rows per thread
#define TPB   128          // NROWS / RR threads per batch
#define BIGF  1e8f

__device__ float g_part[BATCH];

__device__ __forceinline__ float softmin3(float a, float b, float c) {
    float mn = fminf(fminf(a, b), c);
    float s  = __expf(mn - a) + __expf(mn - b) + __expf(mn - c);
    return mn - __logf(s);
}

__global__ __launch_bounds__(TPB)
void sdtw_kernel(const float* __restrict__ X, const float* __restrict__ Y) {
    // y stored as float4 chunks, transposed-by-chunk: sy4[c][j], pad 257 to kill bank conflicts
    __shared__ float4 sy4[8 * 257];
    __shared__ float  sy2[MCOLS];
    __shared__ float  bot[2][TPB];

    const int t = threadIdx.x;
    const int b = blockIdx.x;
    const float* xb = X + (size_t)b * NROWS * DDIM;
    const float* yb = Y + (size_t)b * MCOLS * DDIM;

    // ---- stage y into SMEM (chunk-transposed), coalesced global reads ----
    const float4* yb4 = (const float4*)yb;
    for (int k = t; k < MCOLS * 8; k += TPB) {
        int j = k >> 3, c = k & 7;
        sy4[c * 257 + j] = yb4[k];
    }
    // ---- y squared norms ----
    for (int j = t; j < MCOLS; j += TPB) {
        const float4* row = (const float4*)(yb + j * DDIM);
        float acc = 0.f;
        #pragma unroll
        for (int c = 0; c < 8; c++) {
            float4 v = row[c];
            acc += v.x * v.x + v.y * v.y + v.z * v.z + v.w * v.w;
        }
        sy2[j] = acc;
    }

    // ---- load this thread's 2 x-rows into registers ----
    float4 x0[8], x1[8];
    {
        const float4* r0 = (const float4*)(xb + (size_t)(2 * t)     * DDIM);
        const float4* r1 = (const float4*)(xb + (size_t)(2 * t + 1) * DDIM);
        #pragma unroll
        for (int c = 0; c < 8; c++) { x0[c] = r0[c]; x1[c] = r1[c]; }
    }
    float xx0 = 0.f, xx1 = 0.f;
    #pragma unroll
    for (int c = 0; c < 8; c++) {
        xx0 += x0[c].x * x0[c].x + x0[c].y * x0[c].y + x0[c].z * x0[c].z + x0[c].w * x0[c].w;
        xx1 += x1[c].x * x1[c].x + x1[c].y * x1[c].y + x1[c].z * x1[c].z + x1[c].w * x1[c].w;
    }
    __syncthreads();

    // ---- DP state in registers ----
    // left0 = D[base+1][j-1], left1 = D[base+2][j-1], tl = D[base][j-1]  (base = 2t, 1-based DP rows)
    float left0 = BIGF, left1 = BIGF;
    float tl = (t == 0) ? 0.f : BIGF;

    const int STEPS = MCOLS + TPB - 1;   // 383
    for (int s = 0; s < STEPS; s++) {
        int jj = s - t;                  // 0-based y column
        if (jj >= 0 && jj < MCOLS) {
            // up0 = D[base][j] from neighbor thread's bottom row (prev step), row-0 boundary = BIG
            float up0 = BIGF;
            if (t > 0) up0 = bot[(s & 1) ^ 1][t - 1];

            // squared distances for both rows at column jj (2 accumulators per dot for ILP)
            float d0a = 0.f, d0b = 0.f, d1a = 0.f, d1b = 0.f;
            #pragma unroll
            for (int c = 0; c < 8; c += 2) {
                float4 ya = sy4[c * 257 + jj];
                float4 yv2 = sy4[(c + 1) * 257 + jj];
                d0a = fmaf(x0[c].x, ya.x, d0a); d0a = fmaf(x0[c].y, ya.y, d0a);
                d0a = fmaf(x0[c].z, ya.z, d0a); d0a = fmaf(x0[c].w, ya.w, d0a);
                d1a = fmaf(x1[c].x, ya.x, d1a); d1a = fmaf(x1[c].y, ya.y, d1a);
                d1a = fmaf(x1[c].z, ya.z, d1a); d1a = fmaf(x1[c].w, ya.w, d1a);
                d0b = fmaf(x0[c+1].x, yv2.x, d0b); d0b = fmaf(x0[c+1].y, yv2.y, d0b);
                d0b = fmaf(x0[c+1].z, yv2.z, d0b); d0b = fmaf(x0[c+1].w, yv2.w, d0b);
                d1b = fmaf(x1[c+1].x, yv2.x, d1b); d1b = fmaf(x1[c+1].y, yv2.y, d1b);
                d1b = fmaf(x1[c+1].z, yv2.z, d1b); d1b = fmaf(x1[c+1].w, yv2.w, d1b);
            }
            float yy   = sy2[jj];
            float dot0 = d0a + d0b;
            float dot1 = d1a + d1b;
            float dist0 = fmaxf(fmaf(-2.f, dot0, xx0 + yy), 0.f);
            float dist1 = fmaxf(fmaf(-2.f, dot1, xx1 + yy), 0.f);

            // serial 2-cell softmin chain (all register-resident)
            float v0 = dist0 + softmin3(up0, left0, tl);
            float v1 = dist1 + softmin3(v0,  left1, left0);
            tl = up0; left0 = v0; left1 = v1;

            bot[s & 1][t] = v1;
            if (t == TPB - 1 && jj == MCOLS - 1) g_part[b] = v1;  // D[N][M]
        }
        __syncthreads();
    }
}

__global__ void reduce_kernel(float* __restrict__ out) {
    __shared__ float s[BATCH];
    int t = threadIdx.x;
    s[t] = g_part[t];
    __syncthreads();
    for (int o = BATCH / 2; o > 0; o >>= 1) {
        if (t < o) s[t] += s[t + o];
        __syncthreads();
    }
    if (t == 0) out[0] = s[0] / (float)BATCH;
}

extern "C" void kernel_launch(void* const* d_in, const int* in_sizes, int n_in,
                              void* d_out, int out_size) {
    const float* x = (const float*)d_in[0];
    const float* y = (const float*)d_in[1];
    float* out = (float*)d_out;
    sdtw_kernel<<<BATCH, TPB>>>(x, y);
    reduce_kernel<<<1, BATCH>>>(out);
}